// round 5
// baseline (speedup 1.0000x reference)
#include <cuda_runtime.h>
#include <cstdint>

#define B 16
#define S 4096
#define E 2048
#define WIN 64
#define ROWS (B * S)

#define DOT_BLOCKS      (ROWS / 8)          // 8192, 8 rows (warps) per block
#define BLK_PER_BAT     (DOT_BLOCKS / B)    // 512
#define NWIN (S - WIN + 1)                  // 4033
#define WPT  16                             // windows per thread in epilogue

__device__ float g_scores[ROWS];
__device__ int   g_cnt[B];                  // zero-init; reset each run by epilogue block

__global__ __launch_bounds__(256) void fused_kernel(
    const float* __restrict__ x,
    const int*   __restrict__ mask,   // int32 {0,1} or float32 {0.,1.} bit patterns
    const float* __restrict__ W,
    const float* __restrict__ bias,
    float*       __restrict__ out)
{
    const int t    = threadIdx.x;
    const int row  = (blockIdx.x << 3) + (t >> 5);
    const int lane = t & 31;
    const int b    = blockIdx.x / BLK_PER_BAT;

    // ------------------- DOT phase: one warp per row (identical to R3) ----
    {
        const float4* __restrict__ xr = reinterpret_cast<const float4*>(x) + (size_t)row * (E / 4);
        const float4* __restrict__ Wv = reinterpret_cast<const float4*>(W);

        float s0 = 0.f, s1 = 0.f, s2 = 0.f, s3 = 0.f;
        #pragma unroll
        for (int i = 0; i < 16; i += 4) {
            float4 a0 = xr[lane + (i + 0) * 32];
            float4 a1 = xr[lane + (i + 1) * 32];
            float4 a2 = xr[lane + (i + 2) * 32];
            float4 a3 = xr[lane + (i + 3) * 32];
            float4 w0 = Wv[lane + (i + 0) * 32];
            float4 w1 = Wv[lane + (i + 1) * 32];
            float4 w2 = Wv[lane + (i + 2) * 32];
            float4 w3 = Wv[lane + (i + 3) * 32];
            s0 += a0.x * w0.x + a0.y * w0.y + a0.z * w0.z + a0.w * w0.w;
            s1 += a1.x * w1.x + a1.y * w1.y + a1.z * w1.z + a1.w * w1.w;
            s2 += a2.x * w2.x + a2.y * w2.y + a2.z * w2.z + a2.w * w2.w;
            s3 += a3.x * w3.x + a3.y * w3.y + a3.z * w3.z + a3.w * w3.w;
        }
        float sum = (s0 + s1) + (s2 + s3);

        #pragma unroll
        for (int o = 16; o > 0; o >>= 1)
            sum += __shfl_xor_sync(0xFFFFFFFFu, sum, o);

        if (lane == 0) {
            float tot = sum + bias[0];
            g_scores[row] = (mask[row] != 0) ? tot : 0.0f;
        }
    }
    __syncthreads();

    // ------------------- Am I the last block of my batch? -----------------
    __shared__ int is_last;
    if (t == 0) {
        __threadfence();                           // release my scores
        int prev = atomicAdd(&g_cnt[b], 1);
        is_last = (prev == BLK_PER_BAT - 1) ? 1 : 0;
    }
    __syncthreads();
    if (!is_last) return;

    // ------------------- EPILOGUE (one block per batch, natural tail) -----
    __threadfence();                               // order after counter observe

    __shared__ float sm[S];                        // 16 KB
    const float* __restrict__ src = g_scores + (size_t)b * S;
    for (int i = t; i < S; i += 256)
        sm[i] = __ldcg(&src[i]);                   // bypass L1 (cross-SM producers)
    __syncthreads();

    // Sliding-window: thread t owns windows [t*WPT, t*WPT+WPT)
    const int w0 = t * WPT;
    float best = -3.4e38f;
    if (w0 < NWIN) {
        float acc = 0.0f;
        #pragma unroll
        for (int k = 0; k < WIN; k++) acc += sm[w0 + k];
        best = acc;
        #pragma unroll
        for (int j = 1; j < WPT; j++) {
            if (w0 + j < NWIN) {
                acc += sm[w0 + j + WIN - 1] - sm[w0 + j - 1];
                best = fmaxf(best, acc);
            }
        }
    }

    #pragma unroll
    for (int o = 16; o > 0; o >>= 1)
        best = fmaxf(best, __shfl_xor_sync(0xFFFFFFFFu, best, o));

    __shared__ float pm[8];
    if ((t & 31) == 0) pm[t >> 5] = best;
    __syncthreads();
    if (t == 0) {
        float m = pm[0];
        #pragma unroll
        for (int i = 1; i < 8; i++) m = fmaxf(m, pm[i]);
        out[b] = m / (float)WIN;
        g_cnt[b] = 0;                              // reset for graph replay
    }
}

extern "C" void kernel_launch(void* const* d_in, const int* in_sizes, int n_in,
                              void* d_out, int out_size)
{
    const float* x    = (const float*)d_in[0];
    const int*   mask = (const int*)  d_in[1];
    const float* W    = (const float*)d_in[2];
    const float* bias = (const float*)d_in[3];
    float*       out  = (float*)d_out;

    fused_kernel<<<DOT_BLOCKS, 256>>>(x, mask, W, bias, out);
}

// round 7
// speedup vs baseline: 1.1463x; 1.1463x over previous
#include <cuda_runtime.h>
#include <cstdint>

#define B 16
#define S 4096
#define E 2048
#define WIN 64
#define ROWS (B * S)
#define NWIN (S - WIN + 1)   // 4033
#define EPI_THREADS 1024
#define WPT 4                // windows per thread (1024*4 = 4096 >= 4033)

__device__ float g_scores[ROWS];

// ---------------------------------------------------------------------------
// Kernel 1: EXACT R3 dot kernel. One warp per row; MLP-batched float4 loads.
// ---------------------------------------------------------------------------
__global__ __launch_bounds__(256) void dot_kernel(
    const float* __restrict__ x,
    const int*   __restrict__ mask,   // int32 {0,1} or float32 {0.,1.} bit patterns
    const float* __restrict__ W,
    const float* __restrict__ bias)
{
    const int warp = (blockIdx.x * blockDim.x + threadIdx.x) >> 5;  // row id
    const int lane = threadIdx.x & 31;
    if (warp >= ROWS) return;

    const float4* __restrict__ xr = reinterpret_cast<const float4*>(x) + (size_t)warp * (E / 4);
    const float4* __restrict__ Wv = reinterpret_cast<const float4*>(W);

    float s0 = 0.f, s1 = 0.f, s2 = 0.f, s3 = 0.f;
    #pragma unroll
    for (int i = 0; i < 16; i += 4) {
        float4 a0 = xr[lane + (i + 0) * 32];
        float4 a1 = xr[lane + (i + 1) * 32];
        float4 a2 = xr[lane + (i + 2) * 32];
        float4 a3 = xr[lane + (i + 3) * 32];
        float4 w0 = Wv[lane + (i + 0) * 32];
        float4 w1 = Wv[lane + (i + 1) * 32];
        float4 w2 = Wv[lane + (i + 2) * 32];
        float4 w3 = Wv[lane + (i + 3) * 32];
        s0 += a0.x * w0.x + a0.y * w0.y + a0.z * w0.z + a0.w * w0.w;
        s1 += a1.x * w1.x + a1.y * w1.y + a1.z * w1.z + a1.w * w1.w;
        s2 += a2.x * w2.x + a2.y * w2.y + a2.z * w2.z + a2.w * w2.w;
        s3 += a3.x * w3.x + a3.y * w3.y + a3.z * w3.z + a3.w * w3.w;
    }
    float sum = (s0 + s1) + (s2 + s3);

    #pragma unroll
    for (int o = 16; o > 0; o >>= 1)
        sum += __shfl_xor_sync(0xFFFFFFFFu, sum, o);

    if (lane == 0) {
        float tot = sum + bias[0];
        g_scores[warp] = (mask[warp] != 0) ? tot : 0.0f;
    }
}

// ---------------------------------------------------------------------------
// Kernel 2: merged window + final. grid=B, 1024 threads.
// Sliding window: 64 adds then 3 incremental slides per thread.
// ---------------------------------------------------------------------------
__global__ __launch_bounds__(EPI_THREADS) void epilogue_kernel(float* __restrict__ out)
{
    const int b = blockIdx.x;
    const int t = threadIdx.x;

    __shared__ float sm[S];                     // 16 KB
    const float* __restrict__ src = g_scores + (size_t)b * S;
    for (int i = t; i < S; i += EPI_THREADS)
        sm[i] = src[i];
    __syncthreads();

    const int w0 = t * WPT;
    float best = -3.4e38f;
    if (w0 < NWIN) {
        float acc = 0.0f;
        #pragma unroll
        for (int k = 0; k < WIN; k++) acc += sm[w0 + k];
        best = acc;
        #pragma unroll
        for (int j = 1; j < WPT; j++) {
            if (w0 + j < NWIN) {
                acc += sm[w0 + j + WIN - 1] - sm[w0 + j - 1];
                best = fmaxf(best, acc);
            }
        }
    }

    #pragma unroll
    for (int o = 16; o > 0; o >>= 1)
        best = fmaxf(best, __shfl_xor_sync(0xFFFFFFFFu, best, o));

    __shared__ float pm[32];
    if ((t & 31) == 0) pm[t >> 5] = best;
    __syncthreads();

    if (t < 32) {
        float m = pm[t];
        #pragma unroll
        for (int o = 16; o > 0; o >>= 1)
            m = fmaxf(m, __shfl_xor_sync(0xFFFFFFFFu, m, o));
        if (t == 0) out[b] = m / (float)WIN;
    }
}

extern "C" void kernel_launch(void* const* d_in, const int* in_sizes, int n_in,
                              void* d_out, int out_size)
{
    const float* x    = (const float*)d_in[0];
    const int*   mask = (const int*)  d_in[1];
    const float* W    = (const float*)d_in[2];
    const float* bias = (const float*)d_in[3];
    float*       out  = (float*)d_out;

    dot_kernel<<<ROWS / 8, 256>>>(x, mask, W, bias);   // 8 warps/block, 1 row/warp
    epilogue_kernel<<<B, EPI_THREADS>>>(out);
}